// round 1
// baseline (speedup 1.0000x reference)
#include <cuda_runtime.h>
#include <cstdint>

// Problem constants (from reference): B=32, R=256, T=4096
#define T_LEN 4096
#define THREADS 256
#define ITEMS (T_LEN / THREADS)   // 16
#define N_ROWS_MAX 8192
#define EPS 1e-8f

__device__ float g_row_loss[N_ROWS_MAX];

__global__ __launch_bounds__(THREADS) void w2_row_kernel(
    const float* __restrict__ traces,
    const float* __restrict__ t,
    const float* __restrict__ q_raw)
{
    const int row = blockIdx.x;
    const float* __restrict__ x = traces + (size_t)row * T_LEN;
    const float* __restrict__ q = q_raw + (size_t)row * T_LEN;

    __shared__ float sh_s[T_LEN];
    __shared__ float sh_warp[8];
    __shared__ float sh_inv;   // 1 / total integral

    const int tid  = threadIdx.x;
    const int base = tid * ITEMS;
    const int lane = tid & 31;
    const int wid  = tid >> 5;

    // ---- load x and t for this thread's 16 contiguous elements ----
    float tv[ITEMS];
    {
        const float4* x4 = reinterpret_cast<const float4*>(x + base);
        const float4* t4 = reinterpret_cast<const float4*>(t + base);
#pragma unroll
        for (int k = 0; k < ITEMS / 4; k++) {
            float4 xv = x4[k];
            float4 tt = t4[k];
            sh_s[base + 4 * k + 0] = xv.x * xv.x + EPS;
            sh_s[base + 4 * k + 1] = xv.y * xv.y + EPS;
            sh_s[base + 4 * k + 2] = xv.z * xv.z + EPS;
            sh_s[base + 4 * k + 3] = xv.w * xv.w + EPS;
            tv[4 * k + 0] = tt.x;
            tv[4 * k + 1] = tt.y;
            tv[4 * k + 2] = tt.z;
            tv[4 * k + 3] = tt.w;
        }
    }
    __syncthreads();

    // ---- local inclusive scan of trapezoid increments ----
    // e_j = 0.5*(s[j-1]+s[j])*(t[j]-t[j-1]) for j>=1, e_0 = 0
    // cdf_raw[j] = inclusive_scan(e)[j]
    float cdf_local[ITEMS];
    float prev_s, prev_t;
    if (base == 0) { prev_s = sh_s[0]; prev_t = tv[0]; }       // yields e_0 = 0
    else           { prev_s = sh_s[base - 1]; prev_t = __ldg(t + base - 1); }

    float run = 0.0f;
#pragma unroll
    for (int k = 0; k < ITEMS; k++) {
        float sk = sh_s[base + k];
        float e  = 0.5f * (prev_s + sk) * (tv[k] - prev_t);
        run += e;
        cdf_local[k] = run;
        prev_s = sk;
        prev_t = tv[k];
    }

    // ---- block exclusive scan of per-thread totals ----
    float v = run;
#pragma unroll
    for (int o = 1; o < 32; o <<= 1) {
        float u = __shfl_up_sync(0xffffffffu, v, o);
        if (lane >= o) v += u;
    }
    if (lane == 31) sh_warp[wid] = v;
    __syncthreads();
    if (tid == 0) {
        float acc = 0.0f;
#pragma unroll
        for (int i = 0; i < THREADS / 32; i++) {
            float tmp = sh_warp[i];
            sh_warp[i] = acc;       // exclusive warp offset
            acc += tmp;
        }
        sh_inv = 1.0f / acc;        // acc = trapz(s, t) = total integral
    }
    __syncthreads();

    const float inv    = sh_inv;
    const float offset = sh_warp[wid] + (v - run);   // exclusive prefix for this thread

    // t[base-1] (clamped) and t[base+ITEMS] (clamped) for trapz weights
    const float t_lo_edge = (base == 0) ? tv[0] : __ldg(t + base - 1);
    const float t_hi_edge = (base + ITEMS >= T_LEN) ? tv[ITEMS - 1] : __ldg(t + base + ITEMS);

    // ---- interp + loss accumulation ----
    float acc_loss = 0.0f;
#pragma unroll
    for (int k = 0; k < ITEMS; k++) {
        float c = (offset + cdf_local[k]) * inv;     // cdf in [0,1] (+- ulp)
        float pos = c * (float)(T_LEN - 1);
        pos = fminf(fmaxf(pos, 0.0f), (float)(T_LEN - 1));
        int   i = min((int)pos, T_LEN - 2);
        float w = pos - (float)i;
        float q0 = __ldg(q + i);
        float q1 = __ldg(q + i + 1);
        float transport = q0 + w * (q1 - q0);

        float d   = tv[k] - transport;
        float pdf = sh_s[base + k] * inv;

        float tlo = (k == 0)         ? t_lo_edge : tv[k - 1];
        float thi = (k == ITEMS - 1) ? t_hi_edge : tv[k + 1];
        float wt  = 0.5f * (thi - tlo);
        acc_loss += wt * d * d * pdf;
    }

    // ---- block reduce acc_loss ----
#pragma unroll
    for (int o = 16; o > 0; o >>= 1)
        acc_loss += __shfl_xor_sync(0xffffffffu, acc_loss, o);
    __syncthreads();               // reuse sh_warp
    if (lane == 0) sh_warp[wid] = acc_loss;
    __syncthreads();
    if (tid == 0) {
        float s = 0.0f;
#pragma unroll
        for (int i = 0; i < THREADS / 32; i++) s += sh_warp[i];
        g_row_loss[row] = s;
    }
}

__global__ __launch_bounds__(256) void w2_reduce_kernel(int n_rows, float* __restrict__ out)
{
    __shared__ float sh[8];
    float acc = 0.0f;
    for (int i = threadIdx.x; i < n_rows; i += 256)
        acc += g_row_loss[i];
#pragma unroll
    for (int o = 16; o > 0; o >>= 1)
        acc += __shfl_xor_sync(0xffffffffu, acc, o);
    int lane = threadIdx.x & 31, wid = threadIdx.x >> 5;
    if (lane == 0) sh[wid] = acc;
    __syncthreads();
    if (threadIdx.x == 0) {
        float s = 0.0f;
#pragma unroll
        for (int i = 0; i < 8; i++) s += sh[i];
        out[0] = s;
    }
}

extern "C" void kernel_launch(void* const* d_in, const int* in_sizes, int n_in,
                              void* d_out, int out_size)
{
    // Inputs (metadata order): traces [B*R*T], t [T], p [T] (unused: uniform [0,1]),
    // q_raw [B*R*T]. Output: scalar float loss.
    const float* traces = (const float*)d_in[0];
    const float* t      = (const float*)d_in[1];
    const float* q_raw  = (const float*)d_in[3];
    float* out = (float*)d_out;

    int n_rows = in_sizes[0] / T_LEN;
    if (n_rows > N_ROWS_MAX) n_rows = N_ROWS_MAX;

    w2_row_kernel<<<n_rows, THREADS>>>(traces, t, q_raw);
    w2_reduce_kernel<<<1, 256>>>(n_rows, out);
}

// round 2
// speedup vs baseline: 1.0530x; 1.0530x over previous
#include <cuda_runtime.h>
#include <cstdint>

// Problem constants (from reference): B=32, R=256, T=4096
#define T_LEN 4096
#define THREADS 256
#define ITEMS (T_LEN / THREADS)   // 16
#define N_ROWS_MAX 8192
#define EPS 1e-8f

__device__ float g_row_loss[N_ROWS_MAX];

__global__ __launch_bounds__(THREADS) void w2_row_kernel(
    const float* __restrict__ traces,
    const float* __restrict__ t,
    const float* __restrict__ q_raw)
{
    const int row = blockIdx.x;
    const float* __restrict__ x = traces + (size_t)row * T_LEN;
    const float* __restrict__ q = q_raw + (size_t)row * T_LEN;

    __shared__ float sh_s[T_LEN];   // squared+eps trace values
    __shared__ float sh_q[T_LEN];   // staged quantile table (coalesced load, SMEM gather)
    __shared__ float sh_warp[8];
    __shared__ float sh_inv;        // 1 / total integral

    const int tid  = threadIdx.x;
    const int base = tid * ITEMS;
    const int lane = tid & 31;
    const int wid  = tid >> 5;

    // ---- stage q row into SMEM (coalesced float4 across block) ----
    {
        const float4* q4 = reinterpret_cast<const float4*>(q);
        float4* shq4 = reinterpret_cast<float4*>(sh_q);
#pragma unroll
        for (int k = 0; k < T_LEN / 4 / THREADS; k++)
            shq4[tid + k * THREADS] = q4[tid + k * THREADS];
    }

    // ---- load x and t for this thread's 16 contiguous elements ----
    float tv[ITEMS];
    {
        const float4* x4 = reinterpret_cast<const float4*>(x + base);
        const float4* t4 = reinterpret_cast<const float4*>(t + base);
#pragma unroll
        for (int k = 0; k < ITEMS / 4; k++) {
            float4 xv = x4[k];
            float4 tt = t4[k];
            sh_s[base + 4 * k + 0] = xv.x * xv.x + EPS;
            sh_s[base + 4 * k + 1] = xv.y * xv.y + EPS;
            sh_s[base + 4 * k + 2] = xv.z * xv.z + EPS;
            sh_s[base + 4 * k + 3] = xv.w * xv.w + EPS;
            tv[4 * k + 0] = tt.x;
            tv[4 * k + 1] = tt.y;
            tv[4 * k + 2] = tt.z;
            tv[4 * k + 3] = tt.w;
        }
    }
    __syncthreads();

    // ---- local inclusive scan of trapezoid increments ----
    // e_j = 0.5*(s[j-1]+s[j])*(t[j]-t[j-1]) for j>=1, e_0 = 0
    float cdf_local[ITEMS];
    float prev_s, prev_t;
    if (base == 0) { prev_s = sh_s[0]; prev_t = tv[0]; }       // yields e_0 = 0
    else           { prev_s = sh_s[base - 1]; prev_t = __ldg(t + base - 1); }

    float run = 0.0f;
#pragma unroll
    for (int k = 0; k < ITEMS; k++) {
        float sk = sh_s[base + k];
        float e  = 0.5f * (prev_s + sk) * (tv[k] - prev_t);
        run += e;
        cdf_local[k] = run;
        prev_s = sk;
        prev_t = tv[k];
    }

    // ---- block exclusive scan of per-thread totals ----
    float v = run;
#pragma unroll
    for (int o = 1; o < 32; o <<= 1) {
        float u = __shfl_up_sync(0xffffffffu, v, o);
        if (lane >= o) v += u;
    }
    if (lane == 31) sh_warp[wid] = v;
    __syncthreads();
    if (tid == 0) {
        float acc = 0.0f;
#pragma unroll
        for (int i = 0; i < THREADS / 32; i++) {
            float tmp = sh_warp[i];
            sh_warp[i] = acc;       // exclusive warp offset
            acc += tmp;
        }
        sh_inv = 1.0f / acc;        // acc = trapz(s, t) = total integral
    }
    __syncthreads();

    const float inv    = sh_inv;
    const float offset = sh_warp[wid] + (v - run);   // exclusive prefix for this thread

    // t[base-1] (clamped) and t[base+ITEMS] (clamped) for trapz weights
    const float t_lo_edge = (base == 0) ? tv[0] : __ldg(t + base - 1);
    const float t_hi_edge = (base + ITEMS >= T_LEN) ? tv[ITEMS - 1] : __ldg(t + base + ITEMS);

    // ---- interp (SMEM gather) + loss accumulation ----
    float acc_loss = 0.0f;
#pragma unroll
    for (int k = 0; k < ITEMS; k++) {
        float c = (offset + cdf_local[k]) * inv;     // cdf in [0,1] (+- ulp)
        float pos = c * (float)(T_LEN - 1);
        pos = fminf(fmaxf(pos, 0.0f), (float)(T_LEN - 1));
        int   i = min((int)pos, T_LEN - 2);
        float w = pos - (float)i;
        float q0 = sh_q[i];
        float q1 = sh_q[i + 1];
        float transport = q0 + w * (q1 - q0);

        float d   = tv[k] - transport;
        float pdf = sh_s[base + k] * inv;

        float tlo = (k == 0)         ? t_lo_edge : tv[k - 1];
        float thi = (k == ITEMS - 1) ? t_hi_edge : tv[k + 1];
        float wt  = 0.5f * (thi - tlo);
        acc_loss += wt * d * d * pdf;
    }

    // ---- block reduce acc_loss ----
#pragma unroll
    for (int o = 16; o > 0; o >>= 1)
        acc_loss += __shfl_xor_sync(0xffffffffu, acc_loss, o);
    __syncthreads();               // reuse sh_warp
    if (lane == 0) sh_warp[wid] = acc_loss;
    __syncthreads();
    if (tid == 0) {
        float s = 0.0f;
#pragma unroll
        for (int i = 0; i < THREADS / 32; i++) s += sh_warp[i];
        g_row_loss[row] = s;
    }
}

__global__ __launch_bounds__(256) void w2_reduce_kernel(int n_rows, float* __restrict__ out)
{
    __shared__ float sh[8];
    float acc = 0.0f;
    for (int i = threadIdx.x; i < n_rows; i += 256)
        acc += g_row_loss[i];
#pragma unroll
    for (int o = 16; o > 0; o >>= 1)
        acc += __shfl_xor_sync(0xffffffffu, acc, o);
    int lane = threadIdx.x & 31, wid = threadIdx.x >> 5;
    if (lane == 0) sh[wid] = acc;
    __syncthreads();
    if (threadIdx.x == 0) {
        float s = 0.0f;
#pragma unroll
        for (int i = 0; i < 8; i++) s += sh[i];
        out[0] = s;
    }
}

extern "C" void kernel_launch(void* const* d_in, const int* in_sizes, int n_in,
                              void* d_out, int out_size)
{
    // Inputs (metadata order): traces [B*R*T], t [T], p [T] (unused: uniform [0,1]),
    // q_raw [B*R*T]. Output: scalar float loss.
    const float* traces = (const float*)d_in[0];
    const float* t      = (const float*)d_in[1];
    const float* q_raw  = (const float*)d_in[3];
    float* out = (float*)d_out;

    int n_rows = in_sizes[0] / T_LEN;
    if (n_rows > N_ROWS_MAX) n_rows = N_ROWS_MAX;

    w2_row_kernel<<<n_rows, THREADS>>>(traces, t, q_raw);
    w2_reduce_kernel<<<1, 256>>>(n_rows, out);
}

// round 3
// speedup vs baseline: 1.2360x; 1.1738x over previous
#include <cuda_runtime.h>
#include <cstdint>

// Problem constants (from reference): B=32, R=256, T=4096
#define T_LEN 4096
#define THREADS 256
#define K_CH 16                 // chunks: thread t owns j = k*256 + t
#define EPS 1e-8f

__global__ void w2_zero_kernel(float* __restrict__ out) { out[0] = 0.0f; }

__global__ __launch_bounds__(THREADS) void w2_row_kernel(
    const float* __restrict__ traces,
    const float* __restrict__ t,
    const float* __restrict__ q_raw,
    float* __restrict__ out)
{
    const int row = blockIdx.x;
    const float* __restrict__ x = traces + (size_t)row * T_LEN;
    const float* __restrict__ q = q_raw + (size_t)row * T_LEN;

    __shared__ float sh_q[T_LEN];           // staged quantile table
    __shared__ float sh_edge[K_CH * 8];     // s at lane-31 of each (chunk, warp)
    __shared__ float sh_wsum[K_CH * 8];     // per-(chunk,warp) increment sums
    __shared__ float sh_woff[K_CH * 8];     // exclusive warp offsets within chunk
    __shared__ float sh_csum[K_CH];         // chunk totals
    __shared__ float sh_cpre[K_CH + 1];     // exclusive chunk prefix; [K_CH] = total
    __shared__ float sh_red[8];

    const int tid  = threadIdx.x;
    const int lane = tid & 31;
    const int w    = tid >> 5;

    // ---- stage q row into SMEM (coalesced float4) ----
    {
        const float4* q4 = reinterpret_cast<const float4*>(q);
        float4* sq4 = reinterpret_cast<float4*>(sh_q);
#pragma unroll
        for (int k = 0; k < T_LEN / 4 / THREADS; k++)
            sq4[tid + k * THREADS] = q4[tid + k * THREADS];
    }

    // ---- cyclic load: thread owns j = k*256 + tid ----
    float s[K_CH], tc[K_CH], e[K_CH];
#pragma unroll
    for (int k = 0; k < K_CH; k++) {
        int j = k * THREADS + tid;
        float xv = __ldg(x + j);
        s[k]  = xv * xv + EPS;
        tc[k] = __ldg(t + j);
    }
    if (lane == 31) {
#pragma unroll
        for (int k = 0; k < K_CH; k++) sh_edge[k * 8 + w] = s[k];
    }
    __syncthreads();

    // ---- trapezoid increments + per-chunk warp-level inclusive scans ----
    // e_j = 0.5*(s[j-1]+s[j])*(t[j]-t[j-1]), e_0 = 0
#pragma unroll
    for (int k = 0; k < K_CH; k++) {
        int j = k * THREADS + tid;
        float sp = __shfl_up_sync(0xffffffffu, s[k], 1);
        if (lane == 0)
            sp = (w > 0) ? sh_edge[k * 8 + (w - 1)]
                         : ((k > 0) ? sh_edge[(k - 1) * 8 + 7] : s[0]);
        float tp = __ldg(t + (j ? j - 1 : 0));     // j==0 -> tp=t[0] -> e=0
        float v  = 0.5f * (sp + s[k]) * (tc[k] - tp);
#pragma unroll
        for (int o = 1; o < 32; o <<= 1) {
            float u = __shfl_up_sync(0xffffffffu, v, o);
            if (lane >= o) v += u;
        }
        e[k] = v;                                  // inclusive within warp
        if (lane == 31) sh_wsum[k * 8 + w] = v;
    }
    __syncthreads();

    // ---- per-chunk warp offsets + chunk totals ----
    if (tid < K_CH) {
        float acc = 0.0f;
#pragma unroll
        for (int ww = 0; ww < 8; ww++) {
            float u = sh_wsum[tid * 8 + ww];
            sh_woff[tid * 8 + ww] = acc;
            acc += u;
        }
        sh_csum[tid] = acc;
    }
    __syncthreads();

    // ---- exclusive chunk prefix ----
    if (tid == 0) {
        float acc = 0.0f;
#pragma unroll
        for (int k = 0; k < K_CH; k++) {
            float u = sh_csum[k];
            sh_cpre[k] = acc;
            acc += u;
        }
        sh_cpre[K_CH] = acc;                        // total integral = trapz(s, t)
    }
    __syncthreads();

    const float inv = 1.0f / sh_cpre[K_CH];

    // ---- interp (near-conflict-free SMEM gather) + loss ----
    float acc = 0.0f;
#pragma unroll
    for (int k = 0; k < K_CH; k++) {
        int j = k * THREADS + tid;
        float cdf = sh_cpre[k] + sh_woff[k * 8 + w] + e[k];
        float pos = cdf * inv * (float)(T_LEN - 1);
        pos = fminf(fmaxf(pos, 0.0f), (float)(T_LEN - 1));
        int   i  = min((int)pos, T_LEN - 2);
        float fr = pos - (float)i;
        float q0 = sh_q[i];
        float q1 = sh_q[i + 1];
        float transport = q0 + fr * (q1 - q0);

        float tn = (j == T_LEN - 1) ? tc[k] : __ldg(t + j + 1);
        float tp = (j == 0)         ? tc[k] : __ldg(t + j - 1);
        float d  = tc[k] - transport;
        acc += 0.5f * (tn - tp) * d * d * s[k] * inv;
    }

    // ---- block reduce + global atomic ----
#pragma unroll
    for (int o = 16; o > 0; o >>= 1)
        acc += __shfl_xor_sync(0xffffffffu, acc, o);
    if (lane == 0) sh_red[w] = acc;
    __syncthreads();
    if (tid == 0) {
        float ssum = 0.0f;
#pragma unroll
        for (int i = 0; i < 8; i++) ssum += sh_red[i];
        atomicAdd(out, ssum);
    }
}

extern "C" void kernel_launch(void* const* d_in, const int* in_sizes, int n_in,
                              void* d_out, int out_size)
{
    // Inputs (metadata order): traces [B*R*T], t [T], p [T] (uniform [0,1], unused),
    // q_raw [B*R*T]. Output: scalar float loss.
    const float* traces = (const float*)d_in[0];
    const float* t      = (const float*)d_in[1];
    const float* q_raw  = (const float*)d_in[3];
    float* out = (float*)d_out;

    int n_rows = in_sizes[0] / T_LEN;

    w2_zero_kernel<<<1, 1>>>(out);
    w2_row_kernel<<<n_rows, THREADS>>>(traces, t, q_raw, out);
}